// round 10
// baseline (speedup 1.0000x reference)
#include <cuda_runtime.h>
#include <cuda_fp16.h>
#include <math.h>

#define NB 16
#define NA 720
#define ND 1024
#define NH 512
#define NW 512
#define PI_F 3.14159265358979323846f

// Filtered sinogram in fp16: g_v[g2][a][bin] = uint4 record of 8 batches
// (batches 8*g2 .. 8*g2+7, stored as 4 half2). 23.6 MB, L2-resident.
__device__ uint4 g_v[2 * NA * ND];

__device__ __forceinline__ float2 cmulf(float2 a, float2 b) {
    return make_float2(a.x * b.x - a.y * b.y, a.x * b.y + a.y * b.x);
}
__device__ __forceinline__ unsigned int h2_as_u32(__half2 h) {
    return *reinterpret_cast<unsigned int*>(&h);
}
__device__ __forceinline__ __half2 u32_as_h2(unsigned int u) {
    return *reinterpret_cast<__half2*>(&u);
}

// -------------------------------------------------------------------------
// Kernel 1: ramp filter via complex-pair Stockham FFT (filter real & even:
// FFT(u+iv)*f -> re=filt(u), im=filt(v) exactly). Block = (angle a, batch
// pair m). Stores fp16 v into planar array (u32 slot p = m&3).
// -------------------------------------------------------------------------
__global__ __launch_bounds__(512) void fbp_filter_kernel(
    const float* __restrict__ sino, const float* __restrict__ filt)
{
    __shared__ float2 bufA[ND];
    __shared__ float2 bufB[ND];
    __shared__ float2 tw[ND / 2];

    const int a = blockIdx.x;
    const int m = blockIdx.y;       // batches 2m, 2m+1
    const int tid = threadIdx.x;

    const float* u = sino + ((size_t)(2 * m) * NA + a) * ND;
    const float* v = sino + ((size_t)(2 * m + 1) * NA + a) * ND;

    bufA[tid]       = make_float2(u[tid],       v[tid]);
    bufA[tid + 512] = make_float2(u[tid + 512], v[tid + 512]);
    {
        float sv, cv;
        sincosf((-2.0f * PI_F / ND) * (float)tid, &sv, &cv);
        tw[tid] = make_float2(cv, sv);
    }
    __syncthreads();

    float2* x = bufA;
    float2* y = bufB;

    #pragma unroll
    for (int stage = 0; stage < 10; ++stage) {
        const int s  = 1 << stage;
        const int q  = tid & (s - 1);
        const int ps = tid - q;
        float2 aa = x[tid];
        float2 bb = x[tid + 512];
        float2 w = tw[ps];
        y[2 * ps + q]     = make_float2(aa.x + bb.x, aa.y + bb.y);
        y[2 * ps + s + q] = cmulf(make_float2(aa.x - bb.x, aa.y - bb.y), w);
        __syncthreads();
        float2* t = x; x = y; y = t;
    }
    {
        float f0 = filt[tid], f1 = filt[tid + 512];
        float2 aa = x[tid];       aa.x *= f0; aa.y *= f0; x[tid]       = aa;
        float2 bb = x[tid + 512]; bb.x *= f1; bb.y *= f1; x[tid + 512] = bb;
    }
    __syncthreads();
    #pragma unroll
    for (int stage = 0; stage < 10; ++stage) {
        const int s  = 1 << stage;
        const int q  = tid & (s - 1);
        const int ps = tid - q;
        float2 aa = x[tid];
        float2 bb = x[tid + 512];
        float2 w = tw[ps]; w.y = -w.y;
        y[2 * ps + q]     = make_float2(aa.x + bb.x, aa.y + bb.y);
        y[2 * ps + s + q] = cmulf(make_float2(aa.x - bb.x, aa.y - bb.y), w);
        __syncthreads();
        float2* t = x; x = y; y = t;
    }

    const float invN = 1.0f / (float)ND;
    const int g2 = m >> 2;
    const int p  = m & 3;
    unsigned int* ov = (unsigned int*)g_v;
    const size_t base_u = ((size_t)(g2 * NA + a) * ND) * 4;

    {   // bin = tid
        float2 c = x[tid];
        ov[base_u + (size_t)tid * 4 + p] =
            h2_as_u32(__floats2half2_rn(c.x * invN, c.y * invN));
    }
    {   // bin = tid + 512
        float2 c = x[tid + 512];
        ov[base_u + (size_t)(tid + 512) * 4 + p] =
            h2_as_u32(__floats2half2_rn(c.x * invN, c.y * invN));
    }
}

// -------------------------------------------------------------------------
// Kernel 2: backprojection, warp-cooperative v-window + angle pairing.
// Warp tile 8x4 -> per-angle footprint <= 7|c|+3|s| <= 7.62 bins.
// One LDG per TWO angles: lanes 0-15 hold angle k's 16-bin window,
// lanes 16-31 angle k+1's. v(i0) and v(i0+1) both come from the window
// via shuffle; d computed in fp16 (HSUB2).
// bmin analytic (no REDUX): s>=0 so y-min at tile top; x-corner by sign
// of c; -1 safety margin -> idx in [0,10], idx+1 <= 11 <= 15. Bounds:
// bmin in [149, 871], bmin+15 <= 886 < 1024.
// -------------------------------------------------------------------------
__global__ __launch_bounds__(256) void fbp_backproj_kernel(float* __restrict__ out)
{
    __shared__ float4 cs2[NA / 2];   // (c0,s0,c1,s1) per angle pair

    const int tid = threadIdx.x;
    for (int i = tid; i < NA / 2; i += 256) {
        float s0, c0, s1, c1;
        sincosf((PI_F / (float)NA) * (float)(2 * i),     &s0, &c0);
        sincosf((PI_F / (float)NA) * (float)(2 * i + 1), &s1, &c1);
        cs2[i] = make_float4(c0, s0, c1, s1);
    }
    __syncthreads();

    const int wrp  = tid >> 5;
    const int lane = tid & 31;
    const int xb = (blockIdx.x << 4) + ((wrp & 1) << 3);
    const int yb = (blockIdx.y << 4) + ((wrp >> 1) << 2);
    const int x = xb + (lane & 7);
    const int y = yb + (lane >> 3);
    const float px  = (float)x - 0.5f * (float)(NW - 1);
    const float py  = (float)y - 0.5f * (float)(NH - 1);
    const float pxb = (float)xb - 0.5f * (float)(NW - 1);
    const float pyb = (float)yb - 0.5f * (float)(NH - 1);
    const float C   = 0.5f * (float)(ND - 1);

    const int g2 = blockIdx.z;                       // batches 8*g2 .. 8*g2+7
    const uint4* __restrict__ vbase = g_v + (size_t)g2 * NA * ND;
    const int lanehalf = lane >> 4;                  // 0: angle k, 1: angle k+1
    const int lanelow  = lane & 15;

    float acc[8];
    #pragma unroll
    for (int j = 0; j < 8; ++j) acc[j] = 0.0f;

    for (int a0 = 0; a0 < NA; a0 += 8) {
        __half2 h0 = __float2half2_rn(0.0f);
        __half2 h1 = h0, h2 = h0, h3 = h0;

        #pragma unroll
        for (int j = 0; j < 4; ++j) {
            const int a = a0 + 2 * j;
            float4 q = cs2[(a0 >> 1) + j];           // LDS.128 broadcast

            // analytic window minima (warp-uniform values, computed per lane)
            float pxm0 = (q.x < 0.0f) ? pxb + 7.0f : pxb;
            float pxm1 = (q.z < 0.0f) ? pxb + 7.0f : pxb;
            int bmin0 = (int)fmaf(pxm0, q.x, fmaf(pyb, q.y, C)) - 1;
            int bmin1 = (int)fmaf(pxm1, q.z, fmaf(pyb, q.w, C)) - 1;

            // paired cooperative load: one LDG serves two angles
            int asel = a + lanehalf;
            int bsel = lanehalf ? bmin1 : bmin0;
            uint4 r = vbase[asel * ND + bsel + lanelow];

            // ---- angle a (window in lanes 0-15) ----
            {
                float t  = fmaf(px, q.x, fmaf(py, q.y, C));
                int   i0 = (int)t;
                __half2 w2 = __float2half2_rn(t - (float)i0);
                int s0i = i0 - bmin0;                // in [0,10]
                int s1i = s0i + 1;

                __half2 vx = u32_as_h2(__shfl_sync(0xffffffffu, r.x, s0i));
                __half2 vy = u32_as_h2(__shfl_sync(0xffffffffu, r.y, s0i));
                __half2 vz = u32_as_h2(__shfl_sync(0xffffffffu, r.z, s0i));
                __half2 vw = u32_as_h2(__shfl_sync(0xffffffffu, r.w, s0i));
                __half2 ux = u32_as_h2(__shfl_sync(0xffffffffu, r.x, s1i));
                __half2 uy = u32_as_h2(__shfl_sync(0xffffffffu, r.y, s1i));
                __half2 uz = u32_as_h2(__shfl_sync(0xffffffffu, r.z, s1i));
                __half2 uw = u32_as_h2(__shfl_sync(0xffffffffu, r.w, s1i));

                h0 = __hadd2(h0, __hfma2(w2, __hsub2(ux, vx), vx));
                h1 = __hadd2(h1, __hfma2(w2, __hsub2(uy, vy), vy));
                h2 = __hadd2(h2, __hfma2(w2, __hsub2(uz, vz), vz));
                h3 = __hadd2(h3, __hfma2(w2, __hsub2(uw, vw), vw));
            }
            // ---- angle a+1 (window in lanes 16-31) ----
            {
                float t  = fmaf(px, q.z, fmaf(py, q.w, C));
                int   i0 = (int)t;
                __half2 w2 = __float2half2_rn(t - (float)i0);
                int s0i = 16 + i0 - bmin1;           // in [16,26]
                int s1i = s0i + 1;

                __half2 vx = u32_as_h2(__shfl_sync(0xffffffffu, r.x, s0i));
                __half2 vy = u32_as_h2(__shfl_sync(0xffffffffu, r.y, s0i));
                __half2 vz = u32_as_h2(__shfl_sync(0xffffffffu, r.z, s0i));
                __half2 vw = u32_as_h2(__shfl_sync(0xffffffffu, r.w, s0i));
                __half2 ux = u32_as_h2(__shfl_sync(0xffffffffu, r.x, s1i));
                __half2 uy = u32_as_h2(__shfl_sync(0xffffffffu, r.y, s1i));
                __half2 uz = u32_as_h2(__shfl_sync(0xffffffffu, r.z, s1i));
                __half2 uw = u32_as_h2(__shfl_sync(0xffffffffu, r.w, s1i));

                h0 = __hadd2(h0, __hfma2(w2, __hsub2(ux, vx), vx));
                h1 = __hadd2(h1, __hfma2(w2, __hsub2(uy, vy), vy));
                h2 = __hadd2(h2, __hfma2(w2, __hsub2(uz, vz), vz));
                h3 = __hadd2(h3, __hfma2(w2, __hsub2(uw, vw), vw));
            }
        }

        acc[0] += __low2float(h0);  acc[1] += __high2float(h0);
        acc[2] += __low2float(h1);  acc[3] += __high2float(h1);
        acc[4] += __low2float(h2);  acc[5] += __high2float(h2);
        acc[6] += __low2float(h3);  acc[7] += __high2float(h3);
    }

    const float scale = PI_F / (float)NA;
    const size_t pix = (size_t)y * NW + x;
    const size_t HW = (size_t)NH * NW;
    float* dst = out + (size_t)(8 * g2) * HW + pix;
    #pragma unroll
    for (int j = 0; j < 8; ++j)
        dst[(size_t)j * HW] = acc[j] * scale;
}

extern "C" void kernel_launch(void* const* d_in, const int* in_sizes, int n_in,
                              void* d_out, int out_size)
{
    const float* sino = (const float*)d_in[0];   // (16, 720, 1024) fp32
    const float* filt = (const float*)d_in[1];   // (1024,) fp32
    float* out = (float*)d_out;                  // (16, 512, 512) fp32

    dim3 fgrid(NA, NB / 2);
    fbp_filter_kernel<<<fgrid, 512>>>(sino, filt);

    dim3 bgrid(NW / 16, NH / 16, 2);
    fbp_backproj_kernel<<<bgrid, 256>>>(out);
}

// round 11
// speedup vs baseline: 1.0891x; 1.0891x over previous
#include <cuda_runtime.h>
#include <cuda_fp16.h>
#include <math.h>

#define NB 16
#define NA 720
#define ND 1024
#define NH 512
#define NW 512
#define PI_F 3.14159265358979323846f

// Filtered sinogram in fp16: g_v[g2][a][bin] = uint4 record of 8 batches
// (batches 8*g2 .. 8*g2+7, stored as 4 half2). 23.6 MB, L2-resident.
__device__ uint4 g_v[2 * NA * ND];

__device__ __forceinline__ float2 cmulf(float2 a, float2 b) {
    return make_float2(a.x * b.x - a.y * b.y, a.x * b.y + a.y * b.x);
}
__device__ __forceinline__ unsigned int h2_as_u32(__half2 h) {
    return *reinterpret_cast<unsigned int*>(&h);
}
__device__ __forceinline__ __half2 u32_as_h2(unsigned int u) {
    return *reinterpret_cast<__half2*>(&u);
}

// -------------------------------------------------------------------------
// Kernel 1: ramp filter via complex-pair Stockham FFT (filter real & even:
// FFT(u+iv)*f -> re=filt(u), im=filt(v) exactly). Block = (angle a, batch
// pair m). Stores fp16 v into planar array (u32 slot p = m&3).
// -------------------------------------------------------------------------
__global__ __launch_bounds__(512) void fbp_filter_kernel(
    const float* __restrict__ sino, const float* __restrict__ filt)
{
    __shared__ float2 bufA[ND];
    __shared__ float2 bufB[ND];
    __shared__ float2 tw[ND / 2];

    const int a = blockIdx.x;
    const int m = blockIdx.y;       // batches 2m, 2m+1
    const int tid = threadIdx.x;

    const float* u = sino + ((size_t)(2 * m) * NA + a) * ND;
    const float* v = sino + ((size_t)(2 * m + 1) * NA + a) * ND;

    bufA[tid]       = make_float2(u[tid],       v[tid]);
    bufA[tid + 512] = make_float2(u[tid + 512], v[tid + 512]);
    {
        float sv, cv;
        sincosf((-2.0f * PI_F / ND) * (float)tid, &sv, &cv);
        tw[tid] = make_float2(cv, sv);
    }
    __syncthreads();

    float2* x = bufA;
    float2* y = bufB;

    #pragma unroll
    for (int stage = 0; stage < 10; ++stage) {
        const int s  = 1 << stage;
        const int q  = tid & (s - 1);
        const int ps = tid - q;
        float2 aa = x[tid];
        float2 bb = x[tid + 512];
        float2 w = tw[ps];
        y[2 * ps + q]     = make_float2(aa.x + bb.x, aa.y + bb.y);
        y[2 * ps + s + q] = cmulf(make_float2(aa.x - bb.x, aa.y - bb.y), w);
        __syncthreads();
        float2* t = x; x = y; y = t;
    }
    {
        float f0 = filt[tid], f1 = filt[tid + 512];
        float2 aa = x[tid];       aa.x *= f0; aa.y *= f0; x[tid]       = aa;
        float2 bb = x[tid + 512]; bb.x *= f1; bb.y *= f1; x[tid + 512] = bb;
    }
    __syncthreads();
    #pragma unroll
    for (int stage = 0; stage < 10; ++stage) {
        const int s  = 1 << stage;
        const int q  = tid & (s - 1);
        const int ps = tid - q;
        float2 aa = x[tid];
        float2 bb = x[tid + 512];
        float2 w = tw[ps]; w.y = -w.y;
        y[2 * ps + q]     = make_float2(aa.x + bb.x, aa.y + bb.y);
        y[2 * ps + s + q] = cmulf(make_float2(aa.x - bb.x, aa.y - bb.y), w);
        __syncthreads();
        float2* t = x; x = y; y = t;
    }

    const float invN = 1.0f / (float)ND;
    const int g2 = m >> 2;
    const int p  = m & 3;
    unsigned int* ov = (unsigned int*)g_v;
    const size_t base_u = ((size_t)(g2 * NA + a) * ND) * 4;

    {   // bin = tid
        float2 c = x[tid];
        ov[base_u + (size_t)tid * 4 + p] =
            h2_as_u32(__floats2half2_rn(c.x * invN, c.y * invN));
    }
    {   // bin = tid + 512
        float2 c = x[tid + 512];
        ov[base_u + (size_t)(tid + 512) * 4 + p] =
            h2_as_u32(__floats2half2_rn(c.x * invN, c.y * invN));
    }
}

// -------------------------------------------------------------------------
// Kernel 2: backprojection. Warp-cooperative 16-bin v-windows, 2 angles per
// LDG (lanes 0-15: angle 2p, 16-31: angle 2p+1), software-pipelined window
// prefetch, magic-number floor (shuffle index = raw float bits subtract,
// no F2I/I2F), lerp = 2 HFMA2 per batch-word ((1-w)v + w*u).
//
// Magic floor: fr = (t-0.5) + (2^23+2^22) rounds to nearest int i0' in
// {floor(t)-1, floor(t)}; w = t - i0' in [0,1] exact; corner-lane window
// base uses identical arithmetic so idx = bits(fr)-bits(fr_corner)+1 in
// [0,11] <= 15, idx+1 <= 12; window [148, 886] subset of [0,1023].
// -------------------------------------------------------------------------
__global__ __launch_bounds__(256) void fbp_backproj_kernel(float* __restrict__ out)
{
    __shared__ float4 cs2[NA / 2];   // (c0,s0,c1,s1) per angle pair

    const int tid = threadIdx.x;
    for (int i = tid; i < NA / 2; i += 256) {
        float s0, c0, s1, c1;
        sincosf((PI_F / (float)NA) * (float)(2 * i),     &s0, &c0);
        sincosf((PI_F / (float)NA) * (float)(2 * i + 1), &s1, &c1);
        cs2[i] = make_float4(c0, s0, c1, s1);
    }
    __syncthreads();

    const float MAGIC = 12582912.0f;           // 2^23 + 2^22
    const float Cm    = 0.5f * (float)(ND - 1) - 0.5f;   // C - 0.5

    const int wrp  = tid >> 5;
    const int lane = tid & 31;
    const int xb = (blockIdx.x << 4) + ((wrp & 1) << 3);
    const int yb = (blockIdx.y << 4) + ((wrp >> 1) << 2);
    const int x = xb + (lane & 7);
    const int y = yb + (lane >> 3);
    const float px  = (float)x - 0.5f * (float)(NW - 1);
    const float py  = (float)y - 0.5f * (float)(NH - 1);
    const float pxb = (float)xb - 0.5f * (float)(NW - 1);
    const float pyb = (float)yb - 0.5f * (float)(NH - 1);

    const int g2 = blockIdx.z;
    const uint4* __restrict__ vb = g_v + (size_t)g2 * NA * ND;
    const int lanehalf = lane >> 4;
    const int lanelow  = lane & 15;
    const int BM = 0x4B400000;                 // float bits of MAGIC

    float acc[8];
    #pragma unroll
    for (int j = 0; j < 8; ++j) acc[j] = 0.0f;

    // ---- prologue: prefetch pair 0 ----
    int   pc = 0;
    float4 q = cs2[0];
    int bm0, bm1;                              // corner bits per angle
    uint4 r;
    {
        float pxm0 = (q.x < 0.0f) ? pxb + 7.0f : pxb;
        float pxm1 = (q.z < 0.0f) ? pxb + 7.0f : pxb;
        bm0 = __float_as_int(__fadd_rn(fmaf(pxm0, q.x, fmaf(pyb, q.y, Cm)), MAGIC));
        bm1 = __float_as_int(__fadd_rn(fmaf(pxm1, q.z, fmaf(pyb, q.w, Cm)), MAGIC));
        int ib = (lanehalf ? bm1 : bm0) - BM - 1;     // window base bin
        r = vb[lanehalf * ND + ib + lanelow];
    }

    for (int a0 = 0; a0 < NA; a0 += 8) {
        __half2 h0 = __float2half2_rn(0.0f);
        __half2 h1 = h0, h2 = h0, h3 = h0;

        #pragma unroll
        for (int j = 0; j < 4; ++j) {
            // ---- prefetch next pair ----
            int pn = pc + 1; if (pn == NA / 2) pn = 0;
            float4 qn = cs2[pn];
            float pxm0 = (qn.x < 0.0f) ? pxb + 7.0f : pxb;
            float pxm1 = (qn.z < 0.0f) ? pxb + 7.0f : pxb;
            int bm0n = __float_as_int(__fadd_rn(fmaf(pxm0, qn.x, fmaf(pyb, qn.y, Cm)), MAGIC));
            int bm1n = __float_as_int(__fadd_rn(fmaf(pxm1, qn.z, fmaf(pyb, qn.w, Cm)), MAGIC));
            int ibn = (lanehalf ? bm1n : bm0n) - BM - 1;
            uint4 rn = vb[(2 * pn + lanehalf) * ND + ibn + lanelow];

            // ---- process current pair (q, bm0, bm1, r) ----
            // angle 2p (window lanes 0-15)
            {
                float ft = fmaf(px, q.x, fmaf(py, q.y, Cm));
                float fr = __fadd_rn(ft, MAGIC);
                float fi = __fsub_rn(fr, MAGIC);
                float d  = __fsub_rn(ft, fi);          // in [-0.5, 0.5], exact
                __half2 w2  = __float2half2_rn(__fadd_rn(d, 0.5f));
                __half2 ww2 = __float2half2_rn(__fsub_rn(0.5f, d));
                int s0i = __float_as_int(fr) - bm0 + 1;   // in [0,11]
                int s1i = s0i + 1;

                __half2 vx = u32_as_h2(__shfl_sync(0xffffffffu, r.x, s0i));
                __half2 vy = u32_as_h2(__shfl_sync(0xffffffffu, r.y, s0i));
                __half2 vz = u32_as_h2(__shfl_sync(0xffffffffu, r.z, s0i));
                __half2 vw = u32_as_h2(__shfl_sync(0xffffffffu, r.w, s0i));
                __half2 ux = u32_as_h2(__shfl_sync(0xffffffffu, r.x, s1i));
                __half2 uy = u32_as_h2(__shfl_sync(0xffffffffu, r.y, s1i));
                __half2 uz = u32_as_h2(__shfl_sync(0xffffffffu, r.z, s1i));
                __half2 uw = u32_as_h2(__shfl_sync(0xffffffffu, r.w, s1i));

                h0 = __hfma2(ww2, vx, __hfma2(w2, ux, h0));
                h1 = __hfma2(ww2, vy, __hfma2(w2, uy, h1));
                h2 = __hfma2(ww2, vz, __hfma2(w2, uz, h2));
                h3 = __hfma2(ww2, vw, __hfma2(w2, uw, h3));
            }
            // angle 2p+1 (window lanes 16-31)
            {
                float ft = fmaf(px, q.z, fmaf(py, q.w, Cm));
                float fr = __fadd_rn(ft, MAGIC);
                float fi = __fsub_rn(fr, MAGIC);
                float d  = __fsub_rn(ft, fi);
                __half2 w2  = __float2half2_rn(__fadd_rn(d, 0.5f));
                __half2 ww2 = __float2half2_rn(__fsub_rn(0.5f, d));
                int s0i = __float_as_int(fr) - bm1 + 17;  // in [16,27]
                int s1i = s0i + 1;

                __half2 vx = u32_as_h2(__shfl_sync(0xffffffffu, r.x, s0i));
                __half2 vy = u32_as_h2(__shfl_sync(0xffffffffu, r.y, s0i));
                __half2 vz = u32_as_h2(__shfl_sync(0xffffffffu, r.z, s0i));
                __half2 vw = u32_as_h2(__shfl_sync(0xffffffffu, r.w, s0i));
                __half2 ux = u32_as_h2(__shfl_sync(0xffffffffu, r.x, s1i));
                __half2 uy = u32_as_h2(__shfl_sync(0xffffffffu, r.y, s1i));
                __half2 uz = u32_as_h2(__shfl_sync(0xffffffffu, r.z, s1i));
                __half2 uw = u32_as_h2(__shfl_sync(0xffffffffu, r.w, s1i));

                h0 = __hfma2(ww2, vx, __hfma2(w2, ux, h0));
                h1 = __hfma2(ww2, vy, __hfma2(w2, uy, h1));
                h2 = __hfma2(ww2, vz, __hfma2(w2, uz, h2));
                h3 = __hfma2(ww2, vw, __hfma2(w2, uw, h3));
            }

            // rotate pipeline
            q = qn; bm0 = bm0n; bm1 = bm1n; r = rn; pc = pn;
        }

        acc[0] += __low2float(h0);  acc[1] += __high2float(h0);
        acc[2] += __low2float(h1);  acc[3] += __high2float(h1);
        acc[4] += __low2float(h2);  acc[5] += __high2float(h2);
        acc[6] += __low2float(h3);  acc[7] += __high2float(h3);
    }

    const float scale = PI_F / (float)NA;
    const size_t pix = (size_t)y * NW + x;
    const size_t HW = (size_t)NH * NW;
    float* dst = out + (size_t)(8 * g2) * HW + pix;
    #pragma unroll
    for (int j = 0; j < 8; ++j)
        dst[(size_t)j * HW] = acc[j] * scale;
}

extern "C" void kernel_launch(void* const* d_in, const int* in_sizes, int n_in,
                              void* d_out, int out_size)
{
    const float* sino = (const float*)d_in[0];   // (16, 720, 1024) fp32
    const float* filt = (const float*)d_in[1];   // (1024,) fp32
    float* out = (float*)d_out;                  // (16, 512, 512) fp32

    dim3 fgrid(NA, NB / 2);
    fbp_filter_kernel<<<fgrid, 512>>>(sino, filt);

    dim3 bgrid(NW / 16, NH / 16, 2);
    fbp_backproj_kernel<<<bgrid, 256>>>(out);
}

// round 12
// speedup vs baseline: 1.1710x; 1.0752x over previous
#include <cuda_runtime.h>
#include <cuda_fp16.h>
#include <math.h>

#define NB 16
#define NA 720
#define ND 1024
#define NH 512
#define NW 512
#define PI_F 3.14159265358979323846f

// Filtered sinogram in fp16: g_v[g2][a][bin] = uint4 record of 8 batches
// (batches 8*g2 .. 8*g2+7, stored as 4 half2). 23.6 MB, L2-resident.
__device__ uint4 g_v[2 * NA * ND];

__device__ __forceinline__ float2 cmulf(float2 a, float2 b) {
    return make_float2(a.x * b.x - a.y * b.y, a.x * b.y + a.y * b.x);
}
__device__ __forceinline__ unsigned int h2_as_u32(__half2 h) {
    return *reinterpret_cast<unsigned int*>(&h);
}
__device__ __forceinline__ __half2 u32_as_h2(unsigned int u) {
    return *reinterpret_cast<__half2*>(&u);
}

// -------------------------------------------------------------------------
// Kernel 1: ramp filter via complex-pair Stockham FFT (filter real & even:
// FFT(u+iv)*f -> re=filt(u), im=filt(v) exactly). Block = (angle a, batch
// pair m). Stores fp16 v into planar array (u32 slot p = m&3).
// -------------------------------------------------------------------------
__global__ __launch_bounds__(512) void fbp_filter_kernel(
    const float* __restrict__ sino, const float* __restrict__ filt)
{
    __shared__ float2 bufA[ND];
    __shared__ float2 bufB[ND];
    __shared__ float2 tw[ND / 2];

    const int a = blockIdx.x;
    const int m = blockIdx.y;       // batches 2m, 2m+1
    const int tid = threadIdx.x;

    const float* u = sino + ((size_t)(2 * m) * NA + a) * ND;
    const float* v = sino + ((size_t)(2 * m + 1) * NA + a) * ND;

    bufA[tid]       = make_float2(u[tid],       v[tid]);
    bufA[tid + 512] = make_float2(u[tid + 512], v[tid + 512]);
    {
        float sv, cv;
        sincosf((-2.0f * PI_F / ND) * (float)tid, &sv, &cv);
        tw[tid] = make_float2(cv, sv);
    }
    __syncthreads();

    float2* x = bufA;
    float2* y = bufB;

    #pragma unroll
    for (int stage = 0; stage < 10; ++stage) {
        const int s  = 1 << stage;
        const int q  = tid & (s - 1);
        const int ps = tid - q;
        float2 aa = x[tid];
        float2 bb = x[tid + 512];
        float2 w = tw[ps];
        y[2 * ps + q]     = make_float2(aa.x + bb.x, aa.y + bb.y);
        y[2 * ps + s + q] = cmulf(make_float2(aa.x - bb.x, aa.y - bb.y), w);
        __syncthreads();
        float2* t = x; x = y; y = t;
    }
    {
        float f0 = filt[tid], f1 = filt[tid + 512];
        float2 aa = x[tid];       aa.x *= f0; aa.y *= f0; x[tid]       = aa;
        float2 bb = x[tid + 512]; bb.x *= f1; bb.y *= f1; x[tid + 512] = bb;
    }
    __syncthreads();
    #pragma unroll
    for (int stage = 0; stage < 10; ++stage) {
        const int s  = 1 << stage;
        const int q  = tid & (s - 1);
        const int ps = tid - q;
        float2 aa = x[tid];
        float2 bb = x[tid + 512];
        float2 w = tw[ps]; w.y = -w.y;
        y[2 * ps + q]     = make_float2(aa.x + bb.x, aa.y + bb.y);
        y[2 * ps + s + q] = cmulf(make_float2(aa.x - bb.x, aa.y - bb.y), w);
        __syncthreads();
        float2* t = x; x = y; y = t;
    }

    const float invN = 1.0f / (float)ND;
    const int g2 = m >> 2;
    const int p  = m & 3;
    unsigned int* ov = (unsigned int*)g_v;
    const size_t base_u = ((size_t)(g2 * NA + a) * ND) * 4;

    {   // bin = tid
        float2 c = x[tid];
        ov[base_u + (size_t)tid * 4 + p] =
            h2_as_u32(__floats2half2_rn(c.x * invN, c.y * invN));
    }
    {   // bin = tid + 512
        float2 c = x[tid + 512];
        ov[base_u + (size_t)(tid + 512) * 4 + p] =
            h2_as_u32(__floats2half2_rn(c.x * invN, c.y * invN));
    }
}

// -------------------------------------------------------------------------
// Kernel 2: backprojection. Warp-cooperative 16-bin v-windows, 2 angles per
// LDG (lanes 0-15: angle 2p, 16-31: angle 2p+1), magic-number floor
// (shuffle index from raw float bits, no F2I/I2F), lerp = 2 HFMA2/word.
// DEPTH-2 LDG pipeline: each warp keeps 2 window loads in flight so
// ~36 resident warps * 2 outstanding covers the ~250cyc L2 latency
// (1-deep gave 42*1/250*4wf = 0.67 wf/cyc = the measured 67% L1 util).
//
// Magic floor: fr = (t-0.5)+(2^23+2^22) rounds to i0' in {floor(t)-1,
// floor(t)}; w = t-i0' in [0,1] exact; window-corner uses the same
// arithmetic, -1 margin -> idx in [0,11] <= 15, idx+1 <= 12; window
// [148,886] subset of [0,1023].
// -------------------------------------------------------------------------
__global__ __launch_bounds__(256) void fbp_backproj_kernel(float* __restrict__ out)
{
    __shared__ float4 cs2[NA / 2];   // (c0,s0,c1,s1) per angle pair

    const int tid = threadIdx.x;
    for (int i = tid; i < NA / 2; i += 256) {
        float s0, c0, s1, c1;
        sincosf((PI_F / (float)NA) * (float)(2 * i),     &s0, &c0);
        sincosf((PI_F / (float)NA) * (float)(2 * i + 1), &s1, &c1);
        cs2[i] = make_float4(c0, s0, c1, s1);
    }
    __syncthreads();

    const float MAGIC = 12582912.0f;                     // 2^23 + 2^22
    const float Cm    = 0.5f * (float)(ND - 1) - 0.5f;   // C - 0.5

    const int wrp  = tid >> 5;
    const int lane = tid & 31;
    const int xb = (blockIdx.x << 4) + ((wrp & 1) << 3);
    const int yb = (blockIdx.y << 4) + ((wrp >> 1) << 2);
    const int x = xb + (lane & 7);
    const int y = yb + (lane >> 3);
    const float px  = (float)x - 0.5f * (float)(NW - 1);
    const float py  = (float)y - 0.5f * (float)(NH - 1);
    const float pxb = (float)xb - 0.5f * (float)(NW - 1);
    const float pyb = (float)yb - 0.5f * (float)(NH - 1);

    const int g2 = blockIdx.z;
    const uint4* __restrict__ vb = g_v + (size_t)g2 * NA * ND;
    const int lanehalf = lane >> 4;
    const int lanelow  = lane & 15;
    const int BM = 0x4B400000;                 // float bits of MAGIC

    float acc[8];
    #pragma unroll
    for (int j = 0; j < 8; ++j) acc[j] = 0.0f;

    // ---- depth-2 pipeline state ----
    float4 qb[2];
    int    b0b[2], b1b[2];
    uint4  rb[2];

#define PREFETCH(IDX, SLOT) do {                                               \
        int _p = (IDX); if (_p >= NA / 2) _p -= NA / 2;                        \
        float4 _q = cs2[_p];                                                   \
        float _pxm0 = (_q.x < 0.0f) ? pxb + 7.0f : pxb;                        \
        float _pxm1 = (_q.z < 0.0f) ? pxb + 7.0f : pxb;                        \
        int _bm0 = __float_as_int(__fadd_rn(fmaf(_pxm0, _q.x,                  \
                        fmaf(pyb, _q.y, Cm)), MAGIC));                         \
        int _bm1 = __float_as_int(__fadd_rn(fmaf(_pxm1, _q.z,                  \
                        fmaf(pyb, _q.w, Cm)), MAGIC));                         \
        int _ib = (lanehalf ? _bm1 : _bm0) - BM - 1;                           \
        rb[SLOT]  = vb[(2 * _p + lanehalf) * ND + _ib + lanelow];              \
        qb[SLOT]  = _q; b0b[SLOT] = _bm0; b1b[SLOT] = _bm1;                    \
    } while (0)

    PREFETCH(0, 0);
    PREFETCH(1, 1);

    for (int p = 0; p < NA / 2; p += 4) {
        __half2 h0 = __float2half2_rn(0.0f);
        __half2 h1 = h0, h2 = h0, h3 = h0;

        #pragma unroll
        for (int j = 0; j < 4; ++j) {
            const int slot = j & 1;            // p multiple of 4 -> (p+j)&1 == j&1
            // pull current pair into locals, then reuse the slot for idx+2
            float4 q = qb[slot];
            int bm0 = b0b[slot], bm1 = b1b[slot];
            uint4 r = rb[slot];
            PREFETCH(p + j + 2, slot);

            // angle 2p (window lanes 0-15)
            {
                float ft = fmaf(px, q.x, fmaf(py, q.y, Cm));
                float fr = __fadd_rn(ft, MAGIC);
                float fi = __fsub_rn(fr, MAGIC);
                float d  = __fsub_rn(ft, fi);          // [-0.5, 0.5] exact
                __half2 w2  = __float2half2_rn(__fadd_rn(d, 0.5f));
                __half2 ww2 = __float2half2_rn(__fsub_rn(0.5f, d));
                int s0i = __float_as_int(fr) - bm0 + 1;   // [0,11]
                int s1i = s0i + 1;

                __half2 vx = u32_as_h2(__shfl_sync(0xffffffffu, r.x, s0i));
                __half2 vy = u32_as_h2(__shfl_sync(0xffffffffu, r.y, s0i));
                __half2 vz = u32_as_h2(__shfl_sync(0xffffffffu, r.z, s0i));
                __half2 vw = u32_as_h2(__shfl_sync(0xffffffffu, r.w, s0i));
                __half2 ux = u32_as_h2(__shfl_sync(0xffffffffu, r.x, s1i));
                __half2 uy = u32_as_h2(__shfl_sync(0xffffffffu, r.y, s1i));
                __half2 uz = u32_as_h2(__shfl_sync(0xffffffffu, r.z, s1i));
                __half2 uw = u32_as_h2(__shfl_sync(0xffffffffu, r.w, s1i));

                h0 = __hfma2(ww2, vx, __hfma2(w2, ux, h0));
                h1 = __hfma2(ww2, vy, __hfma2(w2, uy, h1));
                h2 = __hfma2(ww2, vz, __hfma2(w2, uz, h2));
                h3 = __hfma2(ww2, vw, __hfma2(w2, uw, h3));
            }
            // angle 2p+1 (window lanes 16-31)
            {
                float ft = fmaf(px, q.z, fmaf(py, q.w, Cm));
                float fr = __fadd_rn(ft, MAGIC);
                float fi = __fsub_rn(fr, MAGIC);
                float d  = __fsub_rn(ft, fi);
                __half2 w2  = __float2half2_rn(__fadd_rn(d, 0.5f));
                __half2 ww2 = __float2half2_rn(__fsub_rn(0.5f, d));
                int s0i = __float_as_int(fr) - bm1 + 17;  // [16,27]
                int s1i = s0i + 1;

                __half2 vx = u32_as_h2(__shfl_sync(0xffffffffu, r.x, s0i));
                __half2 vy = u32_as_h2(__shfl_sync(0xffffffffu, r.y, s0i));
                __half2 vz = u32_as_h2(__shfl_sync(0xffffffffu, r.z, s0i));
                __half2 vw = u32_as_h2(__shfl_sync(0xffffffffu, r.w, s0i));
                __half2 ux = u32_as_h2(__shfl_sync(0xffffffffu, r.x, s1i));
                __half2 uy = u32_as_h2(__shfl_sync(0xffffffffu, r.y, s1i));
                __half2 uz = u32_as_h2(__shfl_sync(0xffffffffu, r.z, s1i));
                __half2 uw = u32_as_h2(__shfl_sync(0xffffffffu, r.w, s1i));

                h0 = __hfma2(ww2, vx, __hfma2(w2, ux, h0));
                h1 = __hfma2(ww2, vy, __hfma2(w2, uy, h1));
                h2 = __hfma2(ww2, vz, __hfma2(w2, uz, h2));
                h3 = __hfma2(ww2, vw, __hfma2(w2, uw, h3));
            }
        }

        acc[0] += __low2float(h0);  acc[1] += __high2float(h0);
        acc[2] += __low2float(h1);  acc[3] += __high2float(h1);
        acc[4] += __low2float(h2);  acc[5] += __high2float(h2);
        acc[6] += __low2float(h3);  acc[7] += __high2float(h3);
    }
#undef PREFETCH

    const float scale = PI_F / (float)NA;
    const size_t pix = (size_t)y * NW + x;
    const size_t HW = (size_t)NH * NW;
    float* dst = out + (size_t)(8 * g2) * HW + pix;
    #pragma unroll
    for (int j = 0; j < 8; ++j)
        dst[(size_t)j * HW] = acc[j] * scale;
}

extern "C" void kernel_launch(void* const* d_in, const int* in_sizes, int n_in,
                              void* d_out, int out_size)
{
    const float* sino = (const float*)d_in[0];   // (16, 720, 1024) fp32
    const float* filt = (const float*)d_in[1];   // (1024,) fp32
    float* out = (float*)d_out;                  // (16, 512, 512) fp32

    dim3 fgrid(NA, NB / 2);
    fbp_filter_kernel<<<fgrid, 512>>>(sino, filt);

    dim3 bgrid(NW / 16, NH / 16, 2);
    fbp_backproj_kernel<<<bgrid, 256>>>(out);
}

// round 14
// speedup vs baseline: 1.1749x; 1.0033x over previous
#include <cuda_runtime.h>
#include <cuda_fp16.h>
#include <math.h>

#define NB 16
#define NA 720
#define ND 1024
#define NH 512
#define NW 512
#define PI_F 3.14159265358979323846f

// Filtered sinogram in fp16: g_v[g2][a][bin] = uint4 record of 8 batches
// (batches 8*g2 .. 8*g2+7, stored as 4 half2). 23.6 MB, L2-resident.
__device__ uint4 g_v[2 * NA * ND];

__device__ __forceinline__ float2 cmulf(float2 a, float2 b) {
    return make_float2(a.x * b.x - a.y * b.y, a.x * b.y + a.y * b.x);
}
__device__ __forceinline__ unsigned int h2_as_u32(__half2 h) {
    return *reinterpret_cast<unsigned int*>(&h);
}
__device__ __forceinline__ __half2 u32_as_h2(unsigned int u) {
    return *reinterpret_cast<__half2*>(&u);
}

// -------------------------------------------------------------------------
// Kernel 1: ramp filter via complex-pair Stockham FFT (filter real & even:
// FFT(u+iv)*f -> re=filt(u), im=filt(v) exactly). Block = (angle a, batch
// pair m). Stores fp16 v into planar array (u32 slot p = m&3).
// -------------------------------------------------------------------------
__global__ __launch_bounds__(512) void fbp_filter_kernel(
    const float* __restrict__ sino, const float* __restrict__ filt)
{
    __shared__ float2 bufA[ND];
    __shared__ float2 bufB[ND];
    __shared__ float2 tw[ND / 2];

    const int a = blockIdx.x;
    const int m = blockIdx.y;       // batches 2m, 2m+1
    const int tid = threadIdx.x;

    const float* u = sino + ((size_t)(2 * m) * NA + a) * ND;
    const float* v = sino + ((size_t)(2 * m + 1) * NA + a) * ND;

    bufA[tid]       = make_float2(u[tid],       v[tid]);
    bufA[tid + 512] = make_float2(u[tid + 512], v[tid + 512]);
    {
        float sv, cv;
        sincosf((-2.0f * PI_F / ND) * (float)tid, &sv, &cv);
        tw[tid] = make_float2(cv, sv);
    }
    __syncthreads();

    float2* x = bufA;
    float2* y = bufB;

    #pragma unroll
    for (int stage = 0; stage < 10; ++stage) {
        const int s  = 1 << stage;
        const int q  = tid & (s - 1);
        const int ps = tid - q;
        float2 aa = x[tid];
        float2 bb = x[tid + 512];
        float2 w = tw[ps];
        y[2 * ps + q]     = make_float2(aa.x + bb.x, aa.y + bb.y);
        y[2 * ps + s + q] = cmulf(make_float2(aa.x - bb.x, aa.y - bb.y), w);
        __syncthreads();
        float2* t = x; x = y; y = t;
    }
    {
        float f0 = filt[tid], f1 = filt[tid + 512];
        float2 aa = x[tid];       aa.x *= f0; aa.y *= f0; x[tid]       = aa;
        float2 bb = x[tid + 512]; bb.x *= f1; bb.y *= f1; x[tid + 512] = bb;
    }
    __syncthreads();
    #pragma unroll
    for (int stage = 0; stage < 10; ++stage) {
        const int s  = 1 << stage;
        const int q  = tid & (s - 1);
        const int ps = tid - q;
        float2 aa = x[tid];
        float2 bb = x[tid + 512];
        float2 w = tw[ps]; w.y = -w.y;
        y[2 * ps + q]     = make_float2(aa.x + bb.x, aa.y + bb.y);
        y[2 * ps + s + q] = cmulf(make_float2(aa.x - bb.x, aa.y - bb.y), w);
        __syncthreads();
        float2* t = x; x = y; y = t;
    }

    const float invN = 1.0f / (float)ND;
    const int g2 = m >> 2;
    const int p  = m & 3;
    unsigned int* ov = (unsigned int*)g_v;
    const size_t base_u = ((size_t)(g2 * NA + a) * ND) * 4;

    {   // bin = tid
        float2 c = x[tid];
        ov[base_u + (size_t)tid * 4 + p] =
            h2_as_u32(__floats2half2_rn(c.x * invN, c.y * invN));
    }
    {   // bin = tid + 512
        float2 c = x[tid + 512];
        ov[base_u + (size_t)(tid + 512) * 4 + p] =
            h2_as_u32(__floats2half2_rn(c.x * invN, c.y * invN));
    }
}

// -------------------------------------------------------------------------
// Kernel 2: backprojection. Warp-cooperative 16-bin v-windows, 2 angles per
// LDG (lanes 0-15: angle 2p, 16-31: angle 2p+1), magic-number floor,
// lerp = 2 HFMA2/word, ww = 1 - w via HSUB2 (fma pipe, not XU cvt).
// DEPTH-3 LDG pipeline with slim slot state ({bm0,bm1,r} only; q re-read
// from smem at consume): ~32 warps * 3 outstanding = 96 LDGs in flight
// covers the ~250cyc L2 latency (depth-2 gave 72 -> 79% L1 util).
// 12-pair unrolled body keeps slot = j%3 compile-time; fp32 flush every
// 4 pairs (8 angles, same cadence as R12 -> same accumulation error).
//
// Magic floor: fr = (t-0.5)+(2^23+2^22) rounds to i0' in {floor(t)-1,
// floor(t)}; w = t-i0' in [0,1] exact; window-corner uses the same
// arithmetic, -1 margin -> idx in [0,11] <= 15, idx+1 <= 12; window
// [148,886] subset of [0,1023].
// -------------------------------------------------------------------------
__global__ __launch_bounds__(256, 4) void fbp_backproj_kernel(float* __restrict__ out)
{
    __shared__ float4 cs2[NA / 2];   // (c0,s0,c1,s1) per angle pair

    const int tid = threadIdx.x;
    for (int i = tid; i < NA / 2; i += 256) {
        float s0, c0, s1, c1;
        sincosf((PI_F / (float)NA) * (float)(2 * i),     &s0, &c0);
        sincosf((PI_F / (float)NA) * (float)(2 * i + 1), &s1, &c1);
        cs2[i] = make_float4(c0, s0, c1, s1);
    }
    __syncthreads();

    const float MAGIC = 12582912.0f;                     // 2^23 + 2^22
    const float Cm    = 0.5f * (float)(ND - 1) - 0.5f;   // C - 0.5

    const int wrp  = tid >> 5;
    const int lane = tid & 31;
    const int xb = (blockIdx.x << 4) + ((wrp & 1) << 3);
    const int yb = (blockIdx.y << 4) + ((wrp >> 1) << 2);
    const int x = xb + (lane & 7);
    const int y = yb + (lane >> 3);
    const float px  = (float)x - 0.5f * (float)(NW - 1);
    const float py  = (float)y - 0.5f * (float)(NH - 1);
    const float pxb = (float)xb - 0.5f * (float)(NW - 1);
    const float pyb = (float)yb - 0.5f * (float)(NH - 1);

    const int g2 = blockIdx.z;
    const uint4* __restrict__ vb = g_v + (size_t)g2 * NA * ND;
    const int lanehalf = lane >> 4;
    const int lanelow  = lane & 15;
    const int BM = 0x4B400000;                 // float bits of MAGIC
    const __half2 ONE2 = __float2half2_rn(1.0f);

    float acc[8];
    #pragma unroll
    for (int j = 0; j < 8; ++j) acc[j] = 0.0f;

    // ---- depth-3 pipeline state (slim: no q kept) ----
    int   b0s[3], b1s[3];
    uint4 rs[3];

#define PREFETCH(IDX, SLOT) do {                                               \
        int _p = (IDX); if (_p >= NA / 2) _p -= NA / 2;                        \
        float4 _q = cs2[_p];                                                   \
        float _pxm0 = (_q.x < 0.0f) ? pxb + 7.0f : pxb;                        \
        float _pxm1 = (_q.z < 0.0f) ? pxb + 7.0f : pxb;                        \
        int _bm0 = __float_as_int(__fadd_rn(fmaf(_pxm0, _q.x,                  \
                        fmaf(pyb, _q.y, Cm)), MAGIC));                         \
        int _bm1 = __float_as_int(__fadd_rn(fmaf(_pxm1, _q.z,                  \
                        fmaf(pyb, _q.w, Cm)), MAGIC));                         \
        int _ib = (lanehalf ? _bm1 : _bm0) - BM - 1;                           \
        rs[SLOT]  = vb[(2 * _p + lanehalf) * ND + _ib + lanelow];              \
        b0s[SLOT] = _bm0; b1s[SLOT] = _bm1;                                    \
    } while (0)

    PREFETCH(0, 0);
    PREFETCH(1, 1);
    PREFETCH(2, 2);

    for (int p = 0; p < NA / 2; p += 12) {       // 30 outer iterations
        __half2 h0 = __float2half2_rn(0.0f);
        __half2 h1 = h0, h2 = h0, h3 = h0;

        #pragma unroll
        for (int j = 0; j < 12; ++j) {
            const int slot = j % 3;              // compile-time (j literal)
            float4 q = cs2[p + j];               // re-read (1 LDS.128, bcast)
            int bm0 = b0s[slot], bm1 = b1s[slot];
            uint4 r = rs[slot];
            PREFETCH(p + j + 3, slot);

            // angle 2(p+j) (window lanes 0-15)
            {
                float ft = fmaf(px, q.x, fmaf(py, q.y, Cm));
                float fr = __fadd_rn(ft, MAGIC);
                float fi = __fsub_rn(fr, MAGIC);
                float d  = __fsub_rn(ft, fi);            // [-0.5, 0.5] exact
                __half2 w2  = __float2half2_rn(__fadd_rn(d, 0.5f));
                __half2 ww2 = __hsub2(ONE2, w2);         // 1-w in fp16 (fma pipe)
                int s0i = __float_as_int(fr) - bm0 + 1;  // [0,11]
                int s1i = s0i + 1;

                __half2 vx = u32_as_h2(__shfl_sync(0xffffffffu, r.x, s0i));
                __half2 vy = u32_as_h2(__shfl_sync(0xffffffffu, r.y, s0i));
                __half2 vz = u32_as_h2(__shfl_sync(0xffffffffu, r.z, s0i));
                __half2 vw = u32_as_h2(__shfl_sync(0xffffffffu, r.w, s0i));
                __half2 ux = u32_as_h2(__shfl_sync(0xffffffffu, r.x, s1i));
                __half2 uy = u32_as_h2(__shfl_sync(0xffffffffu, r.y, s1i));
                __half2 uz = u32_as_h2(__shfl_sync(0xffffffffu, r.z, s1i));
                __half2 uw = u32_as_h2(__shfl_sync(0xffffffffu, r.w, s1i));

                h0 = __hfma2(ww2, vx, __hfma2(w2, ux, h0));
                h1 = __hfma2(ww2, vy, __hfma2(w2, uy, h1));
                h2 = __hfma2(ww2, vz, __hfma2(w2, uz, h2));
                h3 = __hfma2(ww2, vw, __hfma2(w2, uw, h3));
            }
            // angle 2(p+j)+1 (window lanes 16-31)
            {
                float ft = fmaf(px, q.z, fmaf(py, q.w, Cm));
                float fr = __fadd_rn(ft, MAGIC);
                float fi = __fsub_rn(fr, MAGIC);
                float d  = __fsub_rn(ft, fi);
                __half2 w2  = __float2half2_rn(__fadd_rn(d, 0.5f));
                __half2 ww2 = __hsub2(ONE2, w2);
                int s0i = __float_as_int(fr) - bm1 + 17; // [16,27]
                int s1i = s0i + 1;

                __half2 vx = u32_as_h2(__shfl_sync(0xffffffffu, r.x, s0i));
                __half2 vy = u32_as_h2(__shfl_sync(0xffffffffu, r.y, s0i));
                __half2 vz = u32_as_h2(__shfl_sync(0xffffffffu, r.z, s0i));
                __half2 vw = u32_as_h2(__shfl_sync(0xffffffffu, r.w, s0i));
                __half2 ux = u32_as_h2(__shfl_sync(0xffffffffu, r.x, s1i));
                __half2 uy = u32_as_h2(__shfl_sync(0xffffffffu, r.y, s1i));
                __half2 uz = u32_as_h2(__shfl_sync(0xffffffffu, r.z, s1i));
                __half2 uw = u32_as_h2(__shfl_sync(0xffffffffu, r.w, s1i));

                h0 = __hfma2(ww2, vx, __hfma2(w2, ux, h0));
                h1 = __hfma2(ww2, vy, __hfma2(w2, uy, h1));
                h2 = __hfma2(ww2, vz, __hfma2(w2, uz, h2));
                h3 = __hfma2(ww2, vw, __hfma2(w2, uw, h3));
            }

            if ((j & 3) == 3) {                  // flush every 4 pairs = 8 angles
                acc[0] += __low2float(h0);  acc[1] += __high2float(h0);
                acc[2] += __low2float(h1);  acc[3] += __high2float(h1);
                acc[4] += __low2float(h2);  acc[5] += __high2float(h2);
                acc[6] += __low2float(h3);  acc[7] += __high2float(h3);
                h0 = __float2half2_rn(0.0f);
                h1 = h0; h2 = h0; h3 = h0;
            }
        }
    }
#undef PREFETCH

    const float scale = PI_F / (float)NA;
    const size_t pix = (size_t)y * NW + x;
    const size_t HW = (size_t)NH * NW;
    float* dst = out + (size_t)(8 * g2) * HW + pix;
    #pragma unroll
    for (int j = 0; j < 8; ++j)
        dst[(size_t)j * HW] = acc[j] * scale;
}

extern "C" void kernel_launch(void* const* d_in, const int* in_sizes, int n_in,
                              void* d_out, int out_size)
{
    const float* sino = (const float*)d_in[0];   // (16, 720, 1024) fp32
    const float* filt = (const float*)d_in[1];   // (1024,) fp32
    float* out = (float*)d_out;                  // (16, 512, 512) fp32

    dim3 fgrid(NA, NB / 2);
    fbp_filter_kernel<<<fgrid, 512>>>(sino, filt);

    dim3 bgrid(NW / 16, NH / 16, 2);
    fbp_backproj_kernel<<<bgrid, 256>>>(out);
}